// round 13
// baseline (speedup 1.0000x reference)
#include <cuda_runtime.h>
#include <cuda_bf16.h>
#include <cuda_fp16.h>

#define NN     5000   // nodes
#define TIN    12     // input timesteps
#define TTOT   24     // output timesteps
#define BB     16     // batch
#define CC     4      // channels
#define KNB    16     // neighbors
#define NH     4      // heads
#define DIN    48     // T*H
#define DOUT   12     // extrapolated steps

// Transposed fp16 x scratch: xt[n][b][c][t] as __half (t fastest).
// 768 halves = 1536B per node = 192 x 8B chunks; chunk w holds half-positions
// 4w..4w+3, where pos = b*48 + c*12 + t  (bc = w/3, tq = w%3).
__device__ __half g_xth[(size_t)NN * BB * CC * TIN];

typedef unsigned long long ull;

__device__ __forceinline__ ull pk2(float lo, float hi) {
    ull r;
    asm("mov.b64 %0, {%1, %2};" : "=l"(r) : "f"(lo), "f"(hi));
    return r;
}
__device__ __forceinline__ void upk2(float& lo, float& hi, ull v) {
    asm("mov.b64 {%0, %1}, %2;" : "=f"(lo), "=f"(hi) : "l"(v));
}
__device__ __forceinline__ void fma2(ull& d, ull a, ull b, ull c) {
    asm("fma.rn.f32x2 %0, %1, %2, %3;" : "=l"(d) : "l"(a), "l"(b), "l"(c));
}

// ---------------------------------------------------------------------------
// Kernel A (fused): read x (B,T,N,C) once;
//   (1) copy into out[:, 0:12] (coalesced, exact fp32),
//   (2) transpose+convert into g_xth[n][b][c][t] via smem (coalesced writes).
// ---------------------------------------------------------------------------
#define NT 8
#define SROW 772   // 768 floats per node + 4 pad (keeps 16B alignment)

__global__ __launch_bounds__(256) void k_prep(const float* __restrict__ x,
                                              float* __restrict__ out) {
    __shared__ __align__(16) float s[NT][SROW];

    const int tid = threadIdx.x;
    const int n0  = blockIdx.x * NT;
    const int nn  = tid & (NT - 1);
    const int mb  = tid >> 3;            // 0..31
    const int n   = n0 + nn;
    const bool valid = (n < NN);

    const float4* __restrict__ x4 = (const float4*)x;
    float4* __restrict__ out4 = (float4*)out;

    #pragma unroll
    for (int i = 0; i < 6; i++) {
        int m = mb + (i << 5);           // 0..191, m = b*12 + t
        if (valid) {
            float4 v = x4[(size_t)m * NN + n];
            int b = m / TIN, t = m % TIN;
            out4[((size_t)b * TTOT + t) * NN + n] = v;   // exact copy half
            float* sp = &s[nn][b * 48 + t];              // [b][c][t] layout
            sp[0]  = v.x;
            sp[12] = v.y;
            sp[24] = v.z;
            sp[36] = v.w;
        }
    }
    __syncthreads();

    // Phase 2: 96 16B-stores per node, 8 nodes -> 768 stores, 3 iters.
    uint4* __restrict__ xth4 = (uint4*)g_xth;
    union H2U { __half2 h; unsigned u; };
    #pragma unroll
    for (int i = 0; i < 3; i++) {
        int g   = tid + (i << 8);        // 0..767
        int nn2 = g / 96;
        int w   = g - nn2 * 96;
        int n2  = n0 + nn2;
        if (n2 < NN) {
            const float4* sp = (const float4*)&s[nn2][w << 3];
            float4 a = sp[0], b = sp[1];
            H2U h0, h1, h2, h3;
            h0.h = __floats2half2_rn(a.x, a.y);
            h1.h = __floats2half2_rn(a.z, a.w);
            h2.h = __floats2half2_rn(b.x, b.y);
            h3.h = __floats2half2_rn(b.z, b.w);
            uint4 o;
            o.x = h0.u; o.y = h1.u; o.z = h2.u; o.w = h3.u;
            xth4[(size_t)n2 * 96 + w] = o;
        }
    }
}

// ---------------------------------------------------------------------------
// Kernel B: block per node, 192 threads.
// Phase A: thread owns 8B fp16 chunk tid (1 LDG.64/k, depth-3 pipeline);
//   weights read as ONE LDS.128 float4 per k (broadcast) + ALU packing;
//   acc[2 pair][4 head] fp32 f32x2.
// Stage: sagg4[bc * 13 + h*3 + tq] (bc-major, odd float4 pitch).
// Phase B: ALL 192 threads: tid = og*64 + bc; thread computes outputs
//   o = 4*og .. 4*og+3 for its (b,c). sW rows read as broadcast LDS.128.
// ---------------------------------------------------------------------------
#define SPITCH 13   // float4 pitch per bc in sagg (odd -> minimal conflicts)

__global__ __launch_bounds__(192, 8) void k_main(
    const float* __restrict__ dists,
    const float* __restrict__ W,
    const float* __restrict__ bias,
    const int*   __restrict__ neighbors,
    float* __restrict__ out)
{
    __shared__ __align__(16) float4 swf[KNB];        // (e, e^2, e^3, e^4) per k
    __shared__ int   snb[KNB];
    __shared__ __align__(16) float sW[DIN * DOUT];
    __shared__ __align__(16) float sb[16];           // 12 used, 16B-padded
    __shared__ __align__(16) float4 sagg4[64 * SPITCH];

    const int n   = blockIdx.x;
    const int tid = threadIdx.x;

    if (tid < KNB) {
        float d  = dists[n * KNB + tid];
        float e  = __expf(-d * d * (1.0f / 144.0f));   // sigma^2 = 36, H = 4
        float e2 = e * e;
        float4 wv;
        wv.x = e;
        wv.y = e2;
        wv.z = e2 * e;
        wv.w = e2 * e2;
        swf[tid] = wv;
        snb[tid] = neighbors[n * KNB + tid];
    }
    #pragma unroll
    for (int i = tid; i < DIN * DOUT; i += 192) sW[i] = W[i];
    if (tid < DOUT) sb[tid] = bias[tid];
    __syncthreads();

    union F4U { float4 f; ull u[2]; };

    ull acc[2][NH];
    #pragma unroll
    for (int u = 0; u < 2; u++)
        #pragma unroll
        for (int h = 0; h < NH; h++) acc[u][h] = 0ull;

    const uint2* __restrict__ xp = ((const uint2*)g_xth) + tid;

    // Depth-3 software pipeline: 3 independent 8B loads in flight.
    uint2 buf[3];
    buf[0] = xp[(size_t)snb[0] * 192];
    buf[1] = xp[(size_t)snb[1] * 192];
    buf[2] = xp[(size_t)snb[2] * 192];

    #pragma unroll
    for (int k = 0; k < KNB; k++) {
        uint2 raw = buf[k % 3];
        if (k + 3 < KNB) buf[k % 3] = xp[(size_t)snb[k + 3] * 192];

        union { uint2 r; __half2 h[2]; } cv;
        cv.r = raw;
        float2 f0 = __half22float2(cv.h[0]);
        float2 f1 = __half22float2(cv.h[1]);
        ull xv0 = pk2(f0.x, f0.y);
        ull xv1 = pk2(f1.x, f1.y);

        float4 w4 = swf[k];                  // one broadcast LDS.128
        ull wp[NH] = { pk2(w4.x, w4.x), pk2(w4.y, w4.y),
                       pk2(w4.z, w4.z), pk2(w4.w, w4.w) };

        #pragma unroll
        for (int h = 0; h < NH; h++) {
            fma2(acc[0][h], xv0, wp[h], acc[0][h]);
            fma2(acc[1][h], xv1, wp[h], acc[1][h]);
        }
    }

    // Stage: chunk tid -> (bc = tid/3, tq = tid%3), t = 4tq..4tq+3
    {
        const int bc = tid / 3;
        const int tq = tid - bc * 3;
        float4* dst = &sagg4[bc * SPITCH + tq];
        #pragma unroll
        for (int h = 0; h < NH; h++) {
            F4U o;
            o.u[0] = acc[0][h];
            o.u[1] = acc[1][h];
            dst[h * 3] = o.f;
        }
    }
    __syncthreads();

    // Phase B: tid = og*64 + bc; outputs o = 4og..4og+3 for (b,c) = bc.
    {
        const int og = tid >> 6;             // 0..2
        const int bc = tid & 63;
        const float4* __restrict__ fp = &sagg4[bc * SPITCH];

        F4U bb;
        bb.f = *(const float4*)&sb[4 * og];  // uniform broadcast
        ull y0 = bb.u[0], y1 = bb.u[1];

        #pragma unroll
        for (int h = 0; h < NH; h++) {
            #pragma unroll
            for (int tq = 0; tq < 3; tq++) {
                float4 f = fp[h * 3 + tq];
                float fe[4] = { f.x, f.y, f.z, f.w };
                #pragma unroll
                for (int e = 0; e < 4; e++) {
                    int t = 4 * tq + e;
                    ull s = pk2(fe[e], fe[e]);
                    F4U wr;
                    wr.f = *(const float4*)&sW[(t * NH + h) * DOUT + 4 * og];
                    fma2(y0, s, wr.u[0], y0);
                    fma2(y1, s, wr.u[1], y1);
                }
            }
        }

        const int b = bc >> 2;
        const int c = bc & 3;
        float* __restrict__ op_ =
            out + (((size_t)b * TTOT + TIN + 4 * og) * NN + n) * CC + c;
        float ya, yb, yc, yd;
        upk2(ya, yb, y0);
        upk2(yc, yd, y1);
        op_[0]                    = fmaxf(ya, 0.0f);
        op_[(size_t)NN * CC]      = fmaxf(yb, 0.0f);
        op_[(size_t)2 * NN * CC]  = fmaxf(yc, 0.0f);
        op_[(size_t)3 * NN * CC]  = fmaxf(yd, 0.0f);
    }
}

// ---------------------------------------------------------------------------
extern "C" void kernel_launch(void* const* d_in, const int* in_sizes, int n_in,
                              void* d_out, int out_size)
{
    const float* x         = (const float*)d_in[0];
    const float* dists     = (const float*)d_in[1];
    const float* W         = (const float*)d_in[2];
    const float* bias      = (const float*)d_in[3];
    const int*   neighbors = (const int*)  d_in[4];
    float* out = (float*)d_out;

    k_prep<<<(NN + NT - 1) / NT, 256>>>(x, out);
    k_main<<<NN, 192>>>(dists, W, bias, neighbors, out);
}

// round 14
// speedup vs baseline: 1.0528x; 1.0528x over previous
#include <cuda_runtime.h>
#include <cuda_bf16.h>
#include <cuda_fp16.h>

#define NN     5000   // nodes
#define TIN    12     // input timesteps
#define TTOT   24     // output timesteps
#define BB     16     // batch
#define CC     4      // channels
#define KNB    16     // neighbors
#define NH     4      // heads
#define DIN    48     // T*H
#define DOUT   12     // extrapolated steps

// Transposed fp16 x scratch: xt[n][b][c][t] as __half (t fastest).
// 768 halves = 1536B per node = 192 x 8B chunks; chunk w holds half-positions
// 4w..4w+3, where pos = b*48 + c*12 + t.
__device__ __half g_xth[(size_t)NN * BB * CC * TIN];

typedef unsigned long long ull;

__device__ __forceinline__ ull pk2(float lo, float hi) {
    ull r;
    asm("mov.b64 %0, {%1, %2};" : "=l"(r) : "f"(lo), "f"(hi));
    return r;
}
__device__ __forceinline__ void upk2(float& lo, float& hi, ull v) {
    asm("mov.b64 {%0, %1}, %2;" : "=f"(lo), "=f"(hi) : "l"(v));
}
__device__ __forceinline__ void fma2(ull& d, ull a, ull b, ull c) {
    asm("fma.rn.f32x2 %0, %1, %2, %3;" : "=l"(d) : "l"(a), "l"(b), "l"(c));
}

// ---------------------------------------------------------------------------
// Kernel A (fused): read x (B,T,N,C) once;
//   (1) copy into out[:, 0:12] (coalesced, exact fp32),
//   (2) transpose+convert into g_xth[n][b][c][t] via smem (coalesced writes).
// ---------------------------------------------------------------------------
#define NT 8
#define SROW 772   // 768 floats per node + 4 pad (keeps 16B alignment)

__global__ __launch_bounds__(256) void k_prep(const float* __restrict__ x,
                                              float* __restrict__ out) {
    __shared__ __align__(16) float s[NT][SROW];

    const int tid = threadIdx.x;
    const int n0  = blockIdx.x * NT;
    const int nn  = tid & (NT - 1);
    const int mb  = tid >> 3;            // 0..31
    const int n   = n0 + nn;
    const bool valid = (n < NN);

    const float4* __restrict__ x4 = (const float4*)x;
    float4* __restrict__ out4 = (float4*)out;

    #pragma unroll
    for (int i = 0; i < 6; i++) {
        int m = mb + (i << 5);           // 0..191, m = b*12 + t
        if (valid) {
            float4 v = x4[(size_t)m * NN + n];
            int b = m / TIN, t = m % TIN;
            out4[((size_t)b * TTOT + t) * NN + n] = v;   // exact copy half
            float* sp = &s[nn][b * 48 + t];              // [b][c][t] layout
            sp[0]  = v.x;
            sp[12] = v.y;
            sp[24] = v.z;
            sp[36] = v.w;
        }
    }
    __syncthreads();

    // Phase 2: 96 16B-stores per node, 8 nodes -> 768 stores, 3 iters.
    uint4* __restrict__ xth4 = (uint4*)g_xth;
    union H2U { __half2 h; unsigned u; };
    #pragma unroll
    for (int i = 0; i < 3; i++) {
        int g   = tid + (i << 8);        // 0..767
        int nn2 = g / 96;
        int w   = g - nn2 * 96;
        int n2  = n0 + nn2;
        if (n2 < NN) {
            const float4* sp = (const float4*)&s[nn2][w << 3];
            float4 a = sp[0], b = sp[1];
            H2U h0, h1, h2, h3;
            h0.h = __floats2half2_rn(a.x, a.y);
            h1.h = __floats2half2_rn(a.z, a.w);
            h2.h = __floats2half2_rn(b.x, b.y);
            h3.h = __floats2half2_rn(b.z, b.w);
            uint4 o;
            o.x = h0.u; o.y = h1.u; o.z = h2.u; o.w = h3.u;
            xth4[(size_t)n2 * 96 + w] = o;
        }
    }
}

// ---------------------------------------------------------------------------
// Kernel B: block per node, 192 threads.
// Phase A: thread owns the single 8B chunk tid of the 1536B fp16 node row.
//   ALL 16 neighbor loads issued up front (MLP=16, one scoreboard wait),
//   then cvt half2->float2 and fp32 f32x2 accumulation: acc[2 pair][4 head].
// Stage fp32 agg via smem sagg[h][pos] (coalesced STS.128), then
// Phase B: threads 0..63 = (b,c) run the 48x12 linear with warp-uniform
//   broadcast sW reads, ReLU, store. (Identical to the proven R10/R11 epilogue.)
// ---------------------------------------------------------------------------
__global__ __launch_bounds__(192) void k_main(
    const float* __restrict__ dists,
    const float* __restrict__ W,
    const float* __restrict__ bias,
    const int*   __restrict__ neighbors,
    float* __restrict__ out)
{
    __shared__ ull   swp[KNB][NH];                 // packed (w,w) per (k,h)
    __shared__ int   snb[KNB];
    __shared__ __align__(16) float sW[DIN * DOUT];
    __shared__ float sb[DOUT];
    __shared__ __align__(16) float sagg[NH][192 * 4];   // [h][pos] as float4

    const int n   = blockIdx.x;
    const int tid = threadIdx.x;

    if (tid < KNB) {
        float d  = dists[n * KNB + tid];
        float e  = __expf(-d * d * (1.0f / 144.0f));   // sigma^2 = 36, H = 4
        float e2 = e * e;
        swp[tid][0] = pk2(e, e);
        swp[tid][1] = pk2(e2, e2);
        swp[tid][2] = pk2(e2 * e, e2 * e);
        swp[tid][3] = pk2(e2 * e2, e2 * e2);
        snb[tid]    = neighbors[n * KNB + tid];
    }
    #pragma unroll
    for (int i = tid; i < DIN * DOUT; i += 192) sW[i] = W[i];
    if (tid < DOUT) sb[tid] = bias[tid];
    __syncthreads();

    union F4U { float4 f; ull u[2]; };

    ull acc[2][NH];
    #pragma unroll
    for (int u = 0; u < 2; u++)
        #pragma unroll
        for (int h = 0; h < NH; h++) acc[u][h] = 0ull;

    const uint2* __restrict__ xp = ((const uint2*)g_xth) + tid;

    // Full-depth batch: all 16 independent 8B loads in flight (MLP=16).
    uint2 buf[KNB];
    #pragma unroll
    for (int k = 0; k < KNB; k++)
        buf[k] = xp[(size_t)snb[k] * 192];

    #pragma unroll
    for (int k = 0; k < KNB; k++) {
        union { uint2 r; __half2 h[2]; } cv;
        cv.r = buf[k];
        float2 f0 = __half22float2(cv.h[0]);
        float2 f1 = __half22float2(cv.h[1]);
        ull xv0 = pk2(f0.x, f0.y);
        ull xv1 = pk2(f1.x, f1.y);

        #pragma unroll
        for (int h = 0; h < NH; h++) {
            ull w = swp[k][h];
            fma2(acc[0][h], xv0, w, acc[0][h]);
            fma2(acc[1][h], xv1, w, acc[1][h]);
        }
    }

    // Stage aggregated values: chunk tid -> float positions 4*tid..4*tid+3
    float4* __restrict__ sagg4 = (float4*)sagg;
    #pragma unroll
    for (int h = 0; h < NH; h++) {
        F4U o;
        o.u[0] = acc[0][h];
        o.u[1] = acc[1][h];
        sagg4[h * 192 + tid] = o.f;
    }
    __syncthreads();

    if (tid < 64) {
        // (b,c) = tid; its float4 chunks are at index 3*tid + tq (pos = 12*tid)
        ull y2[6];
        #pragma unroll
        for (int op = 0; op < 6; op++) y2[op] = pk2(sb[2 * op], sb[2 * op + 1]);

        #pragma unroll
        for (int tq = 0; tq < 3; tq++) {
            #pragma unroll
            for (int h = 0; h < NH; h++) {
                F4U f;
                f.f = sagg4[h * 192 + 3 * tid + tq];
                float fe[4] = { f.f.x, f.f.y, f.f.z, f.f.w };
                #pragma unroll
                for (int e = 0; e < 4; e++) {
                    int t = 4 * tq + e;
                    ull s = pk2(fe[e], fe[e]);
                    const ull* __restrict__ wr =
                        (const ull*)&sW[(t * NH + h) * DOUT];
                    #pragma unroll
                    for (int op = 0; op < 6; op++)
                        fma2(y2[op], s, wr[op], y2[op]);
                }
            }
        }

        const int b = tid >> 2;
        const int c = tid & 3;
        float* __restrict__ op_ =
            out + (((size_t)b * TTOT + TIN) * NN + n) * CC + c;
        #pragma unroll
        for (int op = 0; op < 6; op++) {
            float y0, y1;
            upk2(y0, y1, y2[op]);
            op_[(size_t)(2 * op)     * NN * CC] = fmaxf(y0, 0.0f);
            op_[(size_t)(2 * op + 1) * NN * CC] = fmaxf(y1, 0.0f);
        }
    }
}

// ---------------------------------------------------------------------------
extern "C" void kernel_launch(void* const* d_in, const int* in_sizes, int n_in,
                              void* d_out, int out_size)
{
    const float* x         = (const float*)d_in[0];
    const float* dists     = (const float*)d_in[1];
    const float* W         = (const float*)d_in[2];
    const float* bias      = (const float*)d_in[3];
    const int*   neighbors = (const int*)  d_in[4];
    float* out = (float*)d_out;

    k_prep<<<(NN + NT - 1) / NT, 256>>>(x, out);
    k_main<<<NN, 192>>>(dists, W, bias, neighbors, out);
}

// round 16
// speedup vs baseline: 1.1231x; 1.0667x over previous
#include <cuda_runtime.h>
#include <cuda_bf16.h>
#include <cuda_fp16.h>

#define NN     5000   // nodes
#define TIN    12     // input timesteps
#define TTOT   24     // output timesteps
#define BB     16     // batch
#define CC     4      // channels
#define KNB    16     // neighbors
#define NH     4      // heads
#define DIN    48     // T*H
#define DOUT   12     // extrapolated steps

// Transposed fp16 x scratch: xt[n][b][c][t] as __half (t fastest).
// 768 halves = 1536B per node = 192 x 8B chunks; chunk w holds half-positions
// 4w..4w+3, where pos = b*48 + c*12 + t.
__device__ __half g_xth[(size_t)NN * BB * CC * TIN];

typedef unsigned long long ull;

__device__ __forceinline__ ull pk2(float lo, float hi) {
    ull r;
    asm("mov.b64 %0, {%1, %2};" : "=l"(r) : "f"(lo), "f"(hi));
    return r;
}
__device__ __forceinline__ void upk2(float& lo, float& hi, ull v) {
    asm("mov.b64 {%0, %1}, %2;" : "=f"(lo), "=f"(hi) : "l"(v));
}
__device__ __forceinline__ void fma2(ull& d, ull a, ull b, ull c) {
    asm("fma.rn.f32x2 %0, %1, %2, %3;" : "=l"(d) : "l"(a), "l"(b), "l"(c));
}

// ---------------------------------------------------------------------------
// Kernel A (fused): read x (B,T,N,C) once;
//   (1) copy into out[:, 0:12] (coalesced, exact fp32),
//   (2) transpose+convert into g_xth[n][b][c][t] via smem (coalesced writes).
// ---------------------------------------------------------------------------
#define NT 8
#define SROW 772   // 768 floats per node + 4 pad (keeps 16B alignment)

__global__ __launch_bounds__(256) void k_prep(const float* __restrict__ x,
                                              float* __restrict__ out) {
    __shared__ __align__(16) float s[NT][SROW];

    const int tid = threadIdx.x;
    const int n0  = blockIdx.x * NT;
    const int nn  = tid & (NT - 1);
    const int mb  = tid >> 3;            // 0..31
    const int n   = n0 + nn;
    const bool valid = (n < NN);

    const float4* __restrict__ x4 = (const float4*)x;
    float4* __restrict__ out4 = (float4*)out;

    #pragma unroll
    for (int i = 0; i < 6; i++) {
        int m = mb + (i << 5);           // 0..191, m = b*12 + t
        if (valid) {
            float4 v = x4[(size_t)m * NN + n];
            int b = m / TIN, t = m % TIN;
            out4[((size_t)b * TTOT + t) * NN + n] = v;   // exact copy half
            float* sp = &s[nn][b * 48 + t];              // [b][c][t] layout
            sp[0]  = v.x;
            sp[12] = v.y;
            sp[24] = v.z;
            sp[36] = v.w;
        }
    }
    __syncthreads();

    // Phase 2: 96 16B-stores per node, 8 nodes -> 768 stores, 3 iters.
    uint4* __restrict__ xth4 = (uint4*)g_xth;
    union H2U { __half2 h; unsigned u; };
    #pragma unroll
    for (int i = 0; i < 3; i++) {
        int g   = tid + (i << 8);        // 0..767
        int nn2 = g / 96;
        int w   = g - nn2 * 96;
        int n2  = n0 + nn2;
        if (n2 < NN) {
            const float4* sp = (const float4*)&s[nn2][w << 3];
            float4 a = sp[0], b = sp[1];
            H2U h0, h1, h2, h3;
            h0.h = __floats2half2_rn(a.x, a.y);
            h1.h = __floats2half2_rn(a.z, a.w);
            h2.h = __floats2half2_rn(b.x, b.y);
            h3.h = __floats2half2_rn(b.z, b.w);
            uint4 o;
            o.x = h0.u; o.y = h1.u; o.z = h2.u; o.w = h3.u;
            xth4[(size_t)n2 * 96 + w] = o;
        }
    }
}

// ---------------------------------------------------------------------------
// Kernel B: block per node, 192 threads.
// Phase A: thread owns the single 8B chunk tid of the 1536B fp16 node row.
//   ALL 16 neighbor loads issued up front (MLP=16); weights read as ONE
//   broadcast LDS.128 per k + ALU packing; acc[2 pair][4 head] fp32 f32x2.
// Stage fp32 agg via smem sagg[h][pos] (coalesced STS.128), then
// Phase B: threads 0..63 = (b,c): 48x12 linear; sW rows read as 3 broadcast
//   LDS.128 per (t,h) instead of 6 LDS.64 per pair. ReLU, store.
// ---------------------------------------------------------------------------
__global__ __launch_bounds__(192) void k_main(
    const float* __restrict__ dists,
    const float* __restrict__ W,
    const float* __restrict__ bias,
    const int*   __restrict__ neighbors,
    float* __restrict__ out)
{
    __shared__ __align__(16) float4 swf[KNB];      // (e, e^2, e^3, e^4) per k
    __shared__ int   snb[KNB];
    __shared__ __align__(16) float sW[DIN * DOUT];
    __shared__ float sb[DOUT];
    __shared__ __align__(16) float sagg[NH][192 * 4];   // [h][pos] as float4

    const int n   = blockIdx.x;
    const int tid = threadIdx.x;

    if (tid < KNB) {
        float d  = dists[n * KNB + tid];
        float e  = __expf(-d * d * (1.0f / 144.0f));   // sigma^2 = 36, H = 4
        float e2 = e * e;
        float4 wv;
        wv.x = e;
        wv.y = e2;
        wv.z = e2 * e;
        wv.w = e2 * e2;
        swf[tid] = wv;
        snb[tid] = neighbors[n * KNB + tid];
    }
    #pragma unroll
    for (int i = tid; i < DIN * DOUT; i += 192) sW[i] = W[i];
    if (tid < DOUT) sb[tid] = bias[tid];
    __syncthreads();

    union F4U { float4 f; ull u[2]; };

    ull acc[2][NH];
    #pragma unroll
    for (int u = 0; u < 2; u++)
        #pragma unroll
        for (int h = 0; h < NH; h++) acc[u][h] = 0ull;

    const uint2* __restrict__ xp = ((const uint2*)g_xth) + tid;

    // Full-depth batch: all 16 independent 8B loads in flight (MLP=16).
    uint2 buf[KNB];
    #pragma unroll
    for (int k = 0; k < KNB; k++)
        buf[k] = xp[(size_t)snb[k] * 192];

    #pragma unroll
    for (int k = 0; k < KNB; k++) {
        union { uint2 r; __half2 h[2]; } cv;
        cv.r = buf[k];
        float2 f0 = __half22float2(cv.h[0]);
        float2 f1 = __half22float2(cv.h[1]);
        ull xv0 = pk2(f0.x, f0.y);
        ull xv1 = pk2(f1.x, f1.y);

        float4 w4 = swf[k];                  // ONE broadcast LDS.128 per k
        ull wp0 = pk2(w4.x, w4.x);
        ull wp1 = pk2(w4.y, w4.y);
        ull wp2 = pk2(w4.z, w4.z);
        ull wp3 = pk2(w4.w, w4.w);

        fma2(acc[0][0], xv0, wp0, acc[0][0]);
        fma2(acc[1][0], xv1, wp0, acc[1][0]);
        fma2(acc[0][1], xv0, wp1, acc[0][1]);
        fma2(acc[1][1], xv1, wp1, acc[1][1]);
        fma2(acc[0][2], xv0, wp2, acc[0][2]);
        fma2(acc[1][2], xv1, wp2, acc[1][2]);
        fma2(acc[0][3], xv0, wp3, acc[0][3]);
        fma2(acc[1][3], xv1, wp3, acc[1][3]);
    }

    // Stage aggregated values: chunk tid -> float positions 4*tid..4*tid+3
    float4* __restrict__ sagg4 = (float4*)sagg;
    #pragma unroll
    for (int h = 0; h < NH; h++) {
        F4U o;
        o.u[0] = acc[0][h];
        o.u[1] = acc[1][h];
        sagg4[h * 192 + tid] = o.f;
    }
    __syncthreads();

    if (tid < 64) {
        // (b,c) = tid; its float4 chunks are at index 3*tid + tq (pos = 12*tid)
        ull y2[6];
        #pragma unroll
        for (int op = 0; op < 6; op++) y2[op] = pk2(sb[2 * op], sb[2 * op + 1]);

        #pragma unroll
        for (int tq = 0; tq < 3; tq++) {
            #pragma unroll
            for (int h = 0; h < NH; h++) {
                F4U f;
                f.f = sagg4[h * 192 + 3 * tid + tq];
                float fe[4] = { f.f.x, f.f.y, f.f.z, f.f.w };
                #pragma unroll
                for (int e = 0; e < 4; e++) {
                    int t = 4 * tq + e;
                    ull s = pk2(fe[e], fe[e]);
                    // 12-float W row = 3 broadcast LDS.128 (was 6 LDS.64)
                    const float4* __restrict__ wr4 =
                        (const float4*)&sW[(t * NH + h) * DOUT];
                    F4U wa, wb, wc;
                    wa.f = wr4[0];
                    wb.f = wr4[1];
                    wc.f = wr4[2];
                    fma2(y2[0], s, wa.u[0], y2[0]);
                    fma2(y2[1], s, wa.u[1], y2[1]);
                    fma2(y2[2], s, wb.u[0], y2[2]);
                    fma2(y2[3], s, wb.u[1], y2[3]);
                    fma2(y2[4], s, wc.u[0], y2[4]);
                    fma2(y2[5], s, wc.u[1], y2[5]);
                }
            }
        }

        const int b = tid >> 2;
        const int c = tid & 3;
        float* __restrict__ op_ =
            out + (((size_t)b * TTOT + TIN) * NN + n) * CC + c;
        #pragma unroll
        for (int op = 0; op < 6; op++) {
            float y0, y1;
            upk2(y0, y1, y2[op]);
            op_[(size_t)(2 * op)     * NN * CC] = fmaxf(y0, 0.0f);
            op_[(size_t)(2 * op + 1) * NN * CC] = fmaxf(y1, 0.0f);
        }
    }
}

// ---------------------------------------------------------------------------
extern "C" void kernel_launch(void* const* d_in, const int* in_sizes, int n_in,
                              void* d_out, int out_size)
{
    const float* x         = (const float*)d_in[0];
    const float* dists     = (const float*)d_in[1];
    const float* W         = (const float*)d_in[2];
    const float* bias      = (const float*)d_in[3];
    const int*   neighbors = (const int*)  d_in[4];
    float* out = (float*)d_out;

    k_prep<<<(NN + NT - 1) / NT, 256>>>(x, out);
    k_main<<<NN, 192>>>(dists, W, bias, neighbors, out);
}